// round 11
// baseline (speedup 1.0000x reference)
#include <cuda_runtime.h>
#include <cstdint>

// Cost volume: out[b,k,h,w] = (1/81) * sum_c x1[b,c,h,w] * x2[b,c,h-i,w-j]
//   i,j in [-4,4], k = (9i+j) mod 81. Zero padding. B=4,C=128,H=128,W=256,D=81.
//
// R10 = R9 math/pipeline (single-barrier cp.async double buffer, 3 i-groups,
// P=4 px/thread, ratio 2.7 FMA/LDS-float) at finer CTA granularity:
// 96 threads = 3 warps (warp g owns di in {3g..3g+2}), tile 4h x 32w,
// grid 1024, launch_bounds(96,4) -> 4 independent CTAs/SM, 12 warps/SM.
// Fixes the 1.73-wave tail (~13% idle) and decouples barrier stalls.

#define Bn 4
#define Cn 128
#define Hn 128
#define Wn 256
#define Dn 81
#define TH 4
#define TW 32
#define CC 4
#define NCH (Cn / CC)       // 32 chunks
#define S2H (TH + 8)        // 12
#define S2W (TW + 8)        // 40
#define NTHR 96

#define S1_F4 (CC * TH * TW / 4)    // 128
#define S2_F4 (CC * S2H * S2W / 4)  // 480

__device__ __forceinline__ void cp16(uint32_t saddr, const float* gptr, bool ok) {
    int sz = ok ? 16 : 0;
    asm volatile("cp.async.cg.shared.global [%0], [%1], 16, %2;\n"
                 :: "r"(saddr), "l"(gptr), "r"(sz));
}
__device__ __forceinline__ void cp_commit() {
    asm volatile("cp.async.commit_group;\n" ::: "memory");
}
template <int N>
__device__ __forceinline__ void cp_wait() {
    asm volatile("cp.async.wait_group %0;\n" :: "n"(N) : "memory");
}

__global__ __launch_bounds__(NTHR, 4)
void costvol_kernel(const float* __restrict__ x1,
                    const float* __restrict__ x2,
                    float* __restrict__ out) {
    __shared__ __align__(16) float s1[2][CC][TH][TW];   // 2 * 2 KB
    __shared__ __align__(16) float s2[2][CC][S2H][S2W]; // 2 * 7.5 KB

    const int w0 = blockIdx.x * TW;
    const int h0 = blockIdx.y * TH;
    const int b  = blockIdx.z;

    const int tid  = threadIdx.x;
    const int g    = tid >> 5;       // warp id = i-group 0..2
    const int lane = tid & 31;
    const int tx   = lane & 7;       // 8 pixel-quads across w
    const int ty   = lane >> 3;      // 4 rows

    const float* x1b = x1 + (size_t)(b * Cn) * Hn * Wn;
    const float* x2b = x2 + (size_t)(b * Cn) * Hn * Wn;

    auto prefetch = [&](int c0, int st) {
        // s1: 128 float4 (2 rounds of 96)
#pragma unroll
        for (int q = 0; q < 2; q++) {
            int f = tid + q * NTHR;
            if (f < S1_F4) {
                int cc  = f >> 5;                // 32 f4 per channel
                int rem = f & 31;
                int hh  = rem >> 3;              // 8 f4 per row
                int k4  = rem & 7;
                uint32_t sa = (uint32_t)__cvta_generic_to_shared(&s1[st][cc][hh][4 * k4]);
                cp16(sa, x1b + (((size_t)(c0 + cc) * Hn + h0 + hh) * Wn + w0 + 4 * k4), true);
            }
        }
        // s2: 480 float4 (5 rounds of 96, exact)
#pragma unroll
        for (int q = 0; q < 5; q++) {
            int f = tid + q * NTHR;
            {
                int cc  = f / (S2H * (S2W / 4));
                int rem = f - cc * (S2H * (S2W / 4));
                int row = rem / (S2W / 4);
                int k4  = rem - row * (S2W / 4);
                int hg  = h0 - 4 + row;
                int wg  = w0 - 4 + 4 * k4;
                bool ok = ((unsigned)hg < (unsigned)Hn) && ((unsigned)wg < (unsigned)Wn);
                const float* gp = ok ? (x2b + (((size_t)cc + c0) * Hn + hg) * (size_t)Wn + wg)
                                     : x2b;
                uint32_t sa = (uint32_t)__cvta_generic_to_shared(&s2[st][cc][row][4 * k4]);
                cp16(sa, gp, ok);
            }
        }
        cp_commit();
    };

    float acc[3][9][4];
#pragma unroll
    for (int u = 0; u < 3; u++)
#pragma unroll
        for (int jj = 0; jj < 9; jj++)
#pragma unroll
            for (int p = 0; p < 4; p++) acc[u][jj][p] = 0.f;

    prefetch(0, 0);

    for (int it = 0; it < NCH; it++) {
        const int st = it & 1;
        cp_wait<0>();
        // Single barrier: publishes chunk `it` AND proves all readers of
        // stage st^1 are done, so the refill below is race-free.
        __syncthreads();
        if (it + 1 < NCH) prefetch((it + 1) * CC, st ^ 1);

#pragma unroll
        for (int cc = 0; cc < CC; cc++) {
            const float4 av = *(const float4*)&s1[st][cc][ty][4 * tx];
            const float a[4] = {av.x, av.y, av.z, av.w};
#pragma unroll
            for (int u = 0; u < 3; u++) {
                const float* rp = &s2[st][cc][ty + 8 - 3 * g - u][4 * tx];
                float wnd[12];
#pragma unroll
                for (int m = 0; m < 12; m += 4) {
                    float4 t = *(const float4*)(rp + m);   // aligned LDS.128
                    wnd[m] = t.x; wnd[m + 1] = t.y; wnd[m + 2] = t.z; wnd[m + 3] = t.w;
                }
#pragma unroll
                for (int jj = 0; jj < 9; jj++) {
#pragma unroll
                    for (int p = 0; p < 4; p++)
                        acc[u][jj][p] += a[p] * wnd[p + 8 - jj];
                }
            }
        }
    }

    // ---- epilogue: k = (9*ii + jj + 41) mod 81, ii = 3g+u ----
    const float inv = 1.0f / 81.0f;
    const int hg = h0 + ty;
    const int wg = w0 + 4 * tx;
#pragma unroll
    for (int u = 0; u < 3; u++) {
        const int ii = 3 * g + u;
#pragma unroll
        for (int jj = 0; jj < 9; jj++) {
            int k = 9 * ii + jj + 41;
            if (k >= 81) k -= 81;
            float4 v = make_float4(acc[u][jj][0] * inv, acc[u][jj][1] * inv,
                                   acc[u][jj][2] * inv, acc[u][jj][3] * inv);
            *(float4*)(out + (((size_t)((b * Dn + k) * Hn + hg)) * Wn + wg)) = v;
        }
    }
}

extern "C" void kernel_launch(void* const* d_in, const int* in_sizes, int n_in,
                              void* d_out, int out_size) {
    (void)in_sizes; (void)n_in; (void)out_size;
    const float* x1 = (const float*)d_in[0];
    const float* x2 = (const float*)d_in[1];
    float* out = (float*)d_out;
    dim3 grid(Wn / TW, Hn / TH, Bn);   // (8, 32, 4) = 1024 blocks
    costvol_kernel<<<grid, NTHR>>>(x1, x2, out);
}